// round 10
// baseline (speedup 1.0000x reference)
#include <cuda_runtime.h>
#include <cuda_bf16.h>
#include <cstdint>

#define BB   8
#define TT   128
#define EE   30522
#define HH   1000
#define SS   64
#define NZ   10000
#define EN   40522   // E + NZ
#define G4H  4000    // 4*H

// ---------------- static scratch ----------------
__device__ float g_preg[BB*TT*G4H];
__device__ float g_enc [BB*TT*HH];
__device__ float g_nemb[SS*BB*HH];
__device__ float g_n2l [SS*BB*TT];
__device__ float g_Mt  [HH*HH];
__device__ float g_bias2[HH];
__device__ float g_bias4h[G4H];
__device__ float g_emb [BB*HH];
__device__ float g_applied[BB*HH];
__device__ float g_comb[BB*HH];
__device__ __align__(16) float g_Hs[SS*BB*HH];
__device__ __align__(16) float g_outWT[HH*EE];   // out_W transposed: [H, E]
__device__ float g_cA[BB*HH], g_cB[BB*HH];
__device__ float g_hA[BB*HH], g_hB[BB*HH];

__device__ __forceinline__ float sigmoidf_(float x) { return 1.f / (1.f + expf(-x)); }

// ================= mma.sync helpers (sm_80+ PTX, legal on sm_103) =========
__device__ __forceinline__ uint32_t smem_u32(const void* p) {
    uint32_t a;
    asm("{ .reg .u64 t; cvta.to.shared.u64 t, %1; cvt.u32.u64 %0, t; }" : "=r"(a) : "l"(p));
    return a;
}
__device__ __forceinline__ void ldm4(uint32_t* r, uint32_t addr) {
    asm volatile("ldmatrix.sync.aligned.m8n8.x4.shared.b16 {%0,%1,%2,%3}, [%4];"
        : "=r"(r[0]), "=r"(r[1]), "=r"(r[2]), "=r"(r[3]) : "r"(addr));
}
__device__ __forceinline__ void ldm2(uint32_t* r, uint32_t addr) {
    asm volatile("ldmatrix.sync.aligned.m8n8.x2.shared.b16 {%0,%1}, [%2];"
        : "=r"(r[0]), "=r"(r[1]) : "r"(addr));
}
__device__ __forceinline__ void mma16816(float* c, const uint32_t* a, const uint32_t* b) {
    asm volatile(
        "mma.sync.aligned.m16n8k16.row.col.f32.bf16.bf16.f32 "
        "{%0,%1,%2,%3}, {%4,%5,%6,%7}, {%8,%9}, {%0,%1,%2,%3};"
        : "+f"(c[0]), "+f"(c[1]), "+f"(c[2]), "+f"(c[3])
        : "r"(a[0]), "r"(a[1]), "r"(a[2]), "r"(a[3]), "r"(b[0]), "r"(b[1]));
}
__device__ __forceinline__ uint32_t pack_bf16(__nv_bfloat16 lo, __nv_bfloat16 hi) {
    return ((uint32_t)__bfloat16_as_ushort(hi) << 16) | (uint32_t)__bfloat16_as_ushort(lo);
}

// ================= split-bf16 (3-pass) tensor-core GEMM =====================
// C[m*ldc+n] = sum_k A[m*lda+k]*B[n*ldb+k] (+bias[n]); 128x128 tile per block.
// All lda/ldb used are EVEN -> float2 global loads are 8B aligned.
#define STR 72                      // padded bf16 row stride (elements)
#define TILE_ELT (128*STR)
#define MMA_SMEM (4*TILE_ELT*2)     // Ahi, Alo, Bhi, Blo = 73728 B

__global__ void __launch_bounds__(256) mma_gemm(
    const float* __restrict__ A, long long lda,
    const float* __restrict__ B, long long ldb,
    const float* __restrict__ bias,
    float* __restrict__ C, long long ldc,
    int M, int N, int K)
{
    extern __shared__ __align__(16) char smem[];
    __nv_bfloat16* sAhi = (__nv_bfloat16*)smem;
    __nv_bfloat16* sAlo = sAhi + TILE_ELT;
    __nv_bfloat16* sBhi = sAlo + TILE_ELT;
    __nv_bfloat16* sBlo = sBhi + TILE_ELT;
    uint32_t aHiB = smem_u32(sAhi), aLoB = smem_u32(sAlo);
    uint32_t bHiB = smem_u32(sBhi), bLoB = smem_u32(sBlo);

    int tid = threadIdx.x, lane = tid & 31, wid = tid >> 5;
    int m0 = blockIdx.y * 128, n0 = blockIdx.x * 128;
    int wm = (wid & 1) * 64, wn = (wid >> 1) * 32;

    float acc[4][4][4];
#pragma unroll
    for (int i = 0; i < 4; i++)
#pragma unroll
        for (int j = 0; j < 4; j++)
#pragma unroll
            for (int q = 0; q < 4; q++) acc[i][j][q] = 0.f;

    int nChunks = (K + 63) / 64;
    for (int ch = 0; ch < nChunks; ch++) {
        int k0g = ch * 64;
        // ---- load + split-convert A tile (128 rows x 32 float2 slots = 4096) ----
#pragma unroll
        for (int it = 0; it < 16; it++) {
            int f = tid + it * 256;
            int row = f >> 5, kf = f & 31;
            int k = kf * 2;
            long long m = m0 + row;
            float2 v = make_float2(0.f, 0.f);
            int kg = k0g + k;
            if (m < M && kg < K) {
                if (kg + 1 < K) v = *(const float2*)(A + m * lda + kg);
                else v.x = A[m * lda + kg];
            }
            __nv_bfloat16 hx = __float2bfloat16(v.x), hy = __float2bfloat16(v.y);
            __nv_bfloat16 lx = __float2bfloat16(v.x - __bfloat162float(hx));
            __nv_bfloat16 ly = __float2bfloat16(v.y - __bfloat162float(hy));
            *(uint32_t*)&sAhi[row * STR + k] = pack_bf16(hx, hy);
            *(uint32_t*)&sAlo[row * STR + k] = pack_bf16(lx, ly);
        }
        // ---- load + split-convert B tile (128 rows x 32 float2 slots = 4096) ----
#pragma unroll
        for (int it = 0; it < 16; it++) {
            int f = tid + it * 256;
            int row = f >> 5, kf = f & 31;
            int k = kf * 2;
            long long n = n0 + row;
            float2 v = make_float2(0.f, 0.f);
            int kg = k0g + k;
            if (n < N && kg < K) {
                if (kg + 1 < K) v = *(const float2*)(B + n * ldb + kg);
                else v.x = B[n * ldb + kg];
            }
            __nv_bfloat16 hx = __float2bfloat16(v.x), hy = __float2bfloat16(v.y);
            __nv_bfloat16 lx = __float2bfloat16(v.x - __bfloat162float(hx));
            __nv_bfloat16 ly = __float2bfloat16(v.y - __bfloat162float(hy));
            *(uint32_t*)&sBhi[row * STR + k] = pack_bf16(hx, hy);
            *(uint32_t*)&sBlo[row * STR + k] = pack_bf16(lx, ly);
        }
        __syncthreads();
        // ---- compute: 3 passes (hi*hi, hi*lo, lo*hi) ----
#pragma unroll
        for (int ks = 0; ks < 4; ks++) {
            int kk = ks * 16;
            uint32_t aF[4][4], bF[4][2];
            uint32_t aOff = (uint32_t)((wm + (lane & 15)) * STR + kk + ((lane >> 4) * 8)) * 2;
            uint32_t bOff = (uint32_t)((wn + (lane & 7)) * STR + kk + (((lane >> 3) & 1) * 8)) * 2;
            // A-hi x B-hi
#pragma unroll
            for (int mt = 0; mt < 4; mt++) ldm4(aF[mt], aHiB + aOff + mt * 16 * STR * 2);
#pragma unroll
            for (int nt = 0; nt < 4; nt++) ldm2(bF[nt], bHiB + bOff + nt * 8 * STR * 2);
#pragma unroll
            for (int mt = 0; mt < 4; mt++)
#pragma unroll
                for (int nt = 0; nt < 4; nt++) mma16816(acc[mt][nt], aF[mt], bF[nt]);
            // A-hi x B-lo
            {
                uint32_t bL[4][2];
#pragma unroll
                for (int nt = 0; nt < 4; nt++) ldm2(bL[nt], bLoB + bOff + nt * 8 * STR * 2);
#pragma unroll
                for (int mt = 0; mt < 4; mt++)
#pragma unroll
                    for (int nt = 0; nt < 4; nt++) mma16816(acc[mt][nt], aF[mt], bL[nt]);
            }
            // A-lo x B-hi
#pragma unroll
            for (int mt = 0; mt < 4; mt++) ldm4(aF[mt], aLoB + aOff + mt * 16 * STR * 2);
#pragma unroll
            for (int mt = 0; mt < 4; mt++)
#pragma unroll
                for (int nt = 0; nt < 4; nt++) mma16816(acc[mt][nt], aF[mt], bF[nt]);
        }
        __syncthreads();
    }
    // ---- epilogue ----
#pragma unroll
    for (int mt = 0; mt < 4; mt++) {
        long long r0 = m0 + wm + mt * 16 + (lane >> 2);
        long long r1 = r0 + 8;
#pragma unroll
        for (int nt = 0; nt < 4; nt++) {
            int c0 = n0 + wn + nt * 8 + (lane & 3) * 2;
            float b0v = 0.f, b1v = 0.f;
            if (bias) {
                if (c0 < N) b0v = bias[c0];
                if (c0 + 1 < N) b1v = bias[c0 + 1];
            }
            if (r0 < M) {
                if (c0 < N)     C[r0 * ldc + c0]     = acc[mt][nt][0] + b0v;
                if (c0 + 1 < N) C[r0 * ldc + c0 + 1] = acc[mt][nt][1] + b1v;
            }
            if (r1 < M) {
                if (c0 < N)     C[r1 * ldc + c0]     = acc[mt][nt][2] + b0v;
                if (c0 + 1 < N) C[r1 * ldc + c0 + 1] = acc[mt][nt][3] + b1v;
            }
        }
    }
}

// ---------------- skinny GEMM (M<=8), atomicAdd into C ----------------
#define SK_NT 32
#define SK_KC 1024
__global__ void __launch_bounds__(256) skinny_gemm_kernel(
    const float* __restrict__ A, long long sAm,
    const float* __restrict__ W, long long sWn,
    float* __restrict__ C, int M, int N, int K)
{
    __shared__ float As[8][SK_KC];
    int n0 = blockIdx.x * SK_NT;
    int k0 = blockIdx.y * SK_KC;
    int kLen = min(SK_KC, K - k0);
    int tid = threadIdx.x;
    for (int m = 0; m < M; m++)
        for (int k = tid; k < SK_KC; k += 256)
            As[m][k] = (k < kLen) ? A[(long long)m * sAm + k0 + k] : 0.f;
    __syncthreads();
    int warp = tid >> 5, lane = tid & 31;
    if (warp < M) {
        for (int nn = 0; nn < SK_NT; nn++) {
            int n = n0 + nn;
            if (n >= N) break;
            const float* wr = W + (long long)n * sWn + k0;
            float s = 0.f;
            for (int i = lane; i < kLen; i += 32) s += As[warp][i] * wr[i];
#pragma unroll
            for (int o = 16; o; o >>= 1) s += __shfl_xor_sync(0xffffffffu, s, o);
            if (lane == 0) atomicAdd(&C[warp * N + n], s);
        }
    }
}

// ---------------- transpose out_W [E,H] -> g_outWT [H,E] ----------------
__global__ void transpose_kernel(const float* __restrict__ src, float* __restrict__ dst)
{
    __shared__ float t[32][33];
    int r0 = blockIdx.y * 32, c0 = blockIdx.x * 32;
#pragma unroll
    for (int i = 0; i < 32; i += 8) {
        int r = r0 + threadIdx.y + i, c = c0 + threadIdx.x;
        if (r < EE && c < HH) t[threadIdx.y + i][threadIdx.x] = src[(long long)r * HH + c];
    }
    __syncthreads();
#pragma unroll
    for (int i = 0; i < 32; i += 8) {
        int rr = c0 + threadIdx.y + i, cc = r0 + threadIdx.x;
        if (rr < HH && cc < EE) dst[(long long)rr * EE + cc] = t[threadIdx.x][threadIdx.y + i];
    }
}

// ---------------- init / copy ----------------
__global__ void init_kernel(float* dst, const float* b1, const float* b2, int n, int period)
{
    int i = blockIdx.x * 256 + threadIdx.x;
    if (i < n) {
        float v = 0.f; int p = i % period;
        if (b1) v += b1[p];
        if (b2) v += b2[p];
        dst[i] = v;
    }
}
__global__ void copy_hfinal_kernel()
{
    int i = blockIdx.x * 256 + threadIdx.x;
    if (i < BB * HH) {
        int b = i / HH, j = i % HH;
        g_hA[i] = g_enc[(b * TT + TT - 1) * HH + j];
    }
}
__global__ void copy_emb0_kernel()
{
    int i = blockIdx.x * 256 + threadIdx.x;
    if (i < BB * HH) g_emb[i] = g_nemb[i];
}

// ---------------- encoder recurrent step ----------------
__global__ void __launch_bounds__(256) enc_step_kernel(const float* __restrict__ Whh, int t)
{
    const float* cIn  = (t & 1) ? g_cB : g_cA;
    float*       cOut = (t & 1) ? g_cA : g_cB;
    int warp = threadIdx.x >> 5, lane = threadIdx.x & 31;
    int j = blockIdx.x * 8 + warp;
    int gate = lane >> 3, b = lane & 7;
    float acc = 0.f;
    if (t > 0) {
        const float* hr = g_enc + (long long)(b * TT + t - 1) * HH;
        const float* wr = Whh + (long long)(gate * HH + j) * HH;
        float a0=0,a1=0,a2=0,a3=0;
#pragma unroll 2
        for (int k = 0; k < HH; k += 4) {
            a0 += hr[k]*wr[k]; a1 += hr[k+1]*wr[k+1];
            a2 += hr[k+2]*wr[k+2]; a3 += hr[k+3]*wr[k+3];
        }
        acc = (a0+a1)+(a2+a3);
    }
    float gv = g_preg[(long long)(b * TT + t) * G4H + gate * HH + j] + acc;
    const unsigned F = 0xffffffffu;
    float gi = __shfl_sync(F, gv, b);
    float gf = __shfl_sync(F, gv, 8 + b);
    float gg = __shfl_sync(F, gv, 16 + b);
    float go = __shfl_sync(F, gv, 24 + b);
    if (gate == 0) {
        float c = sigmoidf_(gf) * cIn[b * HH + j] + sigmoidf_(gi) * tanhf(gg);
        cOut[b * HH + j] = c;
        g_enc[(long long)(b * TT + t) * HH + j] = sigmoidf_(go) * tanhf(c);
    }
}

// ---------------- decoder attention (block per b) ----------------
__global__ void __launch_bounds__(256) dec_attn_kernel(const float* __restrict__ attnW, int s)
{
    const float* hIn = (s & 1) ? g_hB : g_hA;
    __shared__ float sx[2 * HH];
    __shared__ float red[256];
    __shared__ float saw[TT];
    __shared__ float sval;
    int b = blockIdx.x, tid = threadIdx.x;
    for (int k = tid; k < HH; k += 256) {
        sx[k] = g_emb[b * HH + k];
        sx[HH + k] = hIn[b * HH + k];
    }
    __syncthreads();
    int t = tid & 127, half = tid >> 7;
    {
        const float* wr = attnW + (long long)t * (3 * HH) + half * HH;
        const float* xr = sx + half * HH;
        float a0=0,a1=0,a2=0,a3=0;
#pragma unroll 2
        for (int k = 0; k < HH; k += 4) {
            a0 += xr[k]*wr[k]; a1 += xr[k+1]*wr[k+1];
            a2 += xr[k+2]*wr[k+2]; a3 += xr[k+3]*wr[k+3];
        }
        red[tid] = (a0+a1)+(a2+a3);
    }
    __syncthreads();
    if (tid < 128) {
        float l = red[tid] + red[tid + 128] + g_n2l[(s * BB + b) * TT + tid];
        saw[tid] = l; red[tid] = l;
    }
    __syncthreads();
    for (int o = 64; o > 0; o >>= 1) {
        if (tid < o) red[tid] = fmaxf(red[tid], red[tid + o]);
        __syncthreads();
    }
    if (tid == 0) sval = red[0];
    __syncthreads();
    float mx = sval;
    if (tid < 128) { float e = expf(saw[tid] - mx); saw[tid] = e; red[tid] = e; }
    __syncthreads();
    for (int o = 64; o > 0; o >>= 1) {
        if (tid < o) red[tid] += red[tid + o];
        __syncthreads();
    }
    if (tid == 0) sval = red[0];
    __syncthreads();
    float inv = 1.f / sval;
    for (int j = tid; j < HH; j += 256) {
        const float* ep = g_enc + (long long)(b * TT) * HH + j;
        float acc = 0.f;
#pragma unroll 4
        for (int tt = 0; tt < TT; tt++) acc += saw[tt] * ep[(long long)tt * HH];
        g_applied[b * HH + j] = acc * inv;
    }
}

// ---------------- combine + relu ----------------
__global__ void __launch_bounds__(256) dec_comb_kernel(
    const float* __restrict__ combW, const float* __restrict__ combB)
{
    int warp = threadIdx.x >> 5, lane = threadIdx.x & 31;
    int j = blockIdx.x * 8 + warp;
    int b = lane & 7, ch = lane >> 3;
    const float* wr = combW + (long long)j * (2 * HH);
    const float* xe = g_emb + b * HH;
    const float* xa = g_applied + b * HH;
    float s0 = 0.f, s1 = 0.f;
#pragma unroll 2
    for (int i = 0; i < 250; i++) {
        int k = ch + 4 * i;
        s0 += xe[k] * wr[k];
        s1 += xa[k] * wr[HH + k];
    }
    float s = s0 + s1;
    s += __shfl_xor_sync(0xffffffffu, s, 8);
    s += __shfl_xor_sync(0xffffffffu, s, 16);
    if (ch == 0) g_comb[b * HH + j] = fmaxf(s + combB[j], 0.f);
}

// ---------------- decoder LSTM step ----------------
__global__ void __launch_bounds__(256) dec_lstm_kernel(
    const float* __restrict__ Wih, const float* __restrict__ Whh,
    const float* __restrict__ bih, const float* __restrict__ bhh, int s)
{
    const float* hIn  = (s & 1) ? g_hB : g_hA;
    const float* cIn  = (s & 1) ? g_cB : g_cA;
    float*       hOut = (s & 1) ? g_hA : g_hB;
    float*       cOut = (s & 1) ? g_cA : g_cB;
    int warp = threadIdx.x >> 5, lane = threadIdx.x & 31;
    int j = blockIdx.x * 8 + warp;
    int gate = lane >> 3, b = lane & 7;
    int row = gate * HH + j;
    const float* w1 = Wih + (long long)row * HH;
    const float* w2 = Whh + (long long)row * HH;
    const float* x1 = g_comb + b * HH;
    const float* x2 = hIn + b * HH;
    float a0=0,a1=0,a2=0,a3=0;
#pragma unroll 2
    for (int k = 0; k < HH; k += 4) {
        a0 += x1[k]*w1[k] + x2[k]*w2[k];
        a1 += x1[k+1]*w1[k+1] + x2[k+1]*w2[k+1];
        a2 += x1[k+2]*w1[k+2] + x2[k+2]*w2[k+2];
        a3 += x1[k+3]*w1[k+3] + x2[k+3]*w2[k+3];
    }
    float gv = (a0+a1)+(a2+a3) + bih[row] + bhh[row];
    const unsigned F = 0xffffffffu;
    float gi = __shfl_sync(F, gv, b);
    float gf = __shfl_sync(F, gv, 8 + b);
    float gg = __shfl_sync(F, gv, 16 + b);
    float go = __shfl_sync(F, gv, 24 + b);
    if (gate == 0) {
        float c = sigmoidf_(gf) * cIn[b * HH + j] + sigmoidf_(gi) * tanhf(gg);
        float h = sigmoidf_(go) * tanhf(c);
        cOut[b * HH + j] = c;
        hOut[b * HH + j] = h;
        g_Hs[(long long)(s * BB + b) * HH + j] = h;
    }
}

// ---------------- next-step emb via fused Mt ----------------
__global__ void __launch_bounds__(256) dec_embnext_kernel(int s, int snext)
{
    const float* hNew = (s & 1) ? g_hA : g_hB;
    int warp = threadIdx.x >> 5, lane = threadIdx.x & 31;
    int j = blockIdx.x * 8 + warp;
    int b = lane & 7, ch = lane >> 3;
    const float* mr = g_Mt + (long long)j * HH;
    const float* hr = hNew + b * HH;
    float s0 = 0.f;
#pragma unroll 2
    for (int i = 0; i < 250; i++) {
        int k = ch + 4 * i;
        s0 += hr[k] * mr[k];
    }
    s0 += __shfl_xor_sync(0xffffffffu, s0, 8);
    s0 += __shfl_xor_sync(0xffffffffu, s0, 16);
    if (ch == 0)
        g_emb[b * HH + j] = s0 + g_bias2[j] + g_nemb[(long long)(snext * BB + b) * HH + j];
}

// ---------------- launcher ----------------
static void launch_mma(const float* A, long long lda, const float* B, long long ldb,
                       const float* bias, float* C, long long ldc, int M, int N, int K)
{
    dim3 g((N + 127) / 128, (M + 127) / 128);
    mma_gemm<<<g, 256, MMA_SMEM>>>(A, lda, B, ldb, bias, C, ldc, M, N, K);
}

extern "C" void kernel_launch(void* const* d_in, const int* in_sizes, int n_in,
                              void* d_out, int out_size)
{
    const float* input    = (const float*)d_in[0];
    const float* noise1   = (const float*)d_in[2];
    const float* noise2   = (const float*)d_in[3];
    const float* init_dec = (const float*)d_in[4];
    const float* eWih = (const float*)d_in[5];
    const float* eWhh = (const float*)d_in[6];
    const float* ebih = (const float*)d_in[7];
    const float* ebhh = (const float*)d_in[8];
    const float* dWih = (const float*)d_in[9];
    const float* dWhh = (const float*)d_in[10];
    const float* dbih = (const float*)d_in[11];
    const float* dbhh = (const float*)d_in[12];
    const float* embW = (const float*)d_in[13];
    const float* embb = (const float*)d_in[14];
    const float* attW = (const float*)d_in[15];
    const float* attb = (const float*)d_in[16];
    const float* combW = (const float*)d_in[17];
    const float* combb = (const float*)d_in[18];
    const float* outW = (const float*)d_in[19];
    const float* outb = (const float*)d_in[20];
    float* out = (float*)d_out;

    cudaFuncSetAttribute(mma_gemm, cudaFuncAttributeMaxDynamicSharedMemorySize, MMA_SMEM);

    float *preg, *Mt, *nemb, *n2l, *bias2, *bias4h, *emb, *Hs, *cA, *outWT;
    cudaGetSymbolAddress((void**)&preg,   g_preg);
    cudaGetSymbolAddress((void**)&Mt,     g_Mt);
    cudaGetSymbolAddress((void**)&nemb,   g_nemb);
    cudaGetSymbolAddress((void**)&n2l,    g_n2l);
    cudaGetSymbolAddress((void**)&bias2,  g_bias2);
    cudaGetSymbolAddress((void**)&bias4h, g_bias4h);
    cudaGetSymbolAddress((void**)&emb,    g_emb);
    cudaGetSymbolAddress((void**)&Hs,     g_Hs);
    cudaGetSymbolAddress((void**)&cA,     g_cA);
    cudaGetSymbolAddress((void**)&outWT,  g_outWT);

    // small inits
    init_kernel<<<(BB*HH + 255) / 256, 256>>>(cA, nullptr, nullptr, BB*HH, 1);
    init_kernel<<<(G4H + 255) / 256, 256>>>(bias4h, ebih, ebhh, G4H, G4H);
    init_kernel<<<(HH + 255) / 256, 256>>>(bias2, nullptr, nullptr, HH, 1);

    // transpose out_W -> [H, E]
    transpose_kernel<<<dim3((HH + 31) / 32, (EE + 31) / 32), dim3(32, 8)>>>(outW, outWT);

    // big GEMMs on tensor cores (split-bf16 3-pass, direct write + bias)
    launch_mma(input, EE, eWih, EE, bias4h, preg, G4H, BB*TT, G4H, EE);
    launch_mma(embW, EN, outWT, EE, nullptr, Mt, HH, HH, HH, EE);
    launch_mma(noise1, NZ, embW + EE, EN, embb, nemb, HH, SS*BB, HH, NZ);
    launch_mma(noise2, HH, attW + 2*HH, 3*HH, attb, n2l, TT, SS*BB, TT, HH);

    // bias2 = emb_W_E @ out_b (skinny fp32)
    skinny_gemm_kernel<<<dim3(32, 30), 256>>>(outb, 0, embW, EN, bias2, 1, HH, EE);

    // encoder recurrence
    for (int t = 0; t < TT; t++)
        enc_step_kernel<<<125, 256>>>(eWhh, t);
    copy_hfinal_kernel<<<(BB*HH + 255) / 256, 256>>>();

    // decoder step-0 emb
    copy_emb0_kernel<<<(BB*HH + 255) / 256, 256>>>();
    skinny_gemm_kernel<<<dim3(32, 30), 256>>>(init_dec, EE, embW, EN, emb, BB, HH, EE);

    for (int s = 0; s < SS; s++) {
        dec_attn_kernel<<<BB, 256>>>(attW, s);
        dec_comb_kernel<<<125, 256>>>(combW, combb);
        dec_lstm_kernel<<<125, 256>>>(dWih, dWhh, dbih, dbhh, s);
        if (s + 1 < SS) dec_embnext_kernel<<<125, 256>>>(s, s + 1);
    }

    // summary = Hs @ out_W.T + out_b  (tensor cores)
    launch_mma(Hs, HH, outW, HH, outb, out, EE, SS*BB, EE, HH);
}

// round 11
// speedup vs baseline: 1.3924x; 1.3924x over previous
#include <cuda_runtime.h>
#include <cuda_bf16.h>
#include <cstdint>

#define BB   8
#define TT   128
#define EE   30522
#define HH   1000
#define SS   64
#define NZ   10000
#define EN   40522   // E + NZ
#define G4H  4000    // 4*H

// ---------------- static scratch ----------------
__device__ float g_preg[BB*TT*G4H];
__device__ float g_enc [BB*TT*HH];
__device__ float g_nemb[SS*BB*HH];
__device__ float g_n2l [SS*BB*TT];
__device__ float g_Mt  [HH*HH];
__device__ float g_bias2[HH];
__device__ float g_bias4h[G4H];
__device__ float g_emb [BB*HH];
__device__ float g_applied[BB*HH];
__device__ float g_comb[BB*HH];
__device__ __align__(16) float g_Hs[SS*BB*HH];
__device__ __align__(16) float g_outWT[HH*EE];   // out_W transposed: [H, E]
__device__ float g_cA[BB*HH], g_cB[BB*HH];
__device__ float g_hA[BB*HH], g_hB[BB*HH];

__device__ __forceinline__ float sigmoidf_(float x) { return 1.f / (1.f + expf(-x)); }

// ================= mma.sync helpers (sm_80+ PTX, legal on sm_103) =========
__device__ __forceinline__ uint32_t smem_u32(const void* p) {
    uint32_t a;
    asm("{ .reg .u64 t; cvta.to.shared.u64 t, %1; cvt.u32.u64 %0, t; }" : "=r"(a) : "l"(p));
    return a;
}
__device__ __forceinline__ void ldm4(uint32_t* r, uint32_t addr) {
    asm volatile("ldmatrix.sync.aligned.m8n8.x4.shared.b16 {%0,%1,%2,%3}, [%4];"
        : "=r"(r[0]), "=r"(r[1]), "=r"(r[2]), "=r"(r[3]) : "r"(addr));
}
__device__ __forceinline__ void ldm2(uint32_t* r, uint32_t addr) {
    asm volatile("ldmatrix.sync.aligned.m8n8.x2.shared.b16 {%0,%1}, [%2];"
        : "=r"(r[0]), "=r"(r[1]) : "r"(addr));
}
__device__ __forceinline__ void mma16816(float* c, const uint32_t* a, const uint32_t* b) {
    asm volatile(
        "mma.sync.aligned.m16n8k16.row.col.f32.bf16.bf16.f32 "
        "{%0,%1,%2,%3}, {%4,%5,%6,%7}, {%8,%9}, {%0,%1,%2,%3};"
        : "+f"(c[0]), "+f"(c[1]), "+f"(c[2]), "+f"(c[3])
        : "r"(a[0]), "r"(a[1]), "r"(a[2]), "r"(a[3]), "r"(b[0]), "r"(b[1]));
}

// split one float2 into bf16 hi/lo pairs (hi2 = rn(v); lo2 = rn(v - hi2))
__device__ __forceinline__ void split_bf16x2(float2 v, __nv_bfloat162& h2, __nv_bfloat162& l2) {
    h2 = __float22bfloat162_rn(v);
    float2 hf = __bfloat1622float2(h2);
    l2 = __float22bfloat162_rn(make_float2(v.x - hf.x, v.y - hf.y));
}

// ================= split-bf16 (3-pass) tensor-core GEMM =====================
// C[m*ldc+n] = sum_k A[m*lda+k]*B[n*ldb+k] (+bias[n]); 128x128 tile per block.
// All lda/ldb used are EVEN -> float2 global loads are 8B aligned.
#define STR 72                      // padded bf16 row stride (elements)
#define TILE_ELT (128*STR)
#define MMA_SMEM (4*TILE_ELT*2)     // Ahi, Alo, Bhi, Blo = 73728 B

__global__ void __launch_bounds__(256) mma_gemm(
    const float* __restrict__ A, long long lda,
    const float* __restrict__ B, long long ldb,
    const float* __restrict__ bias,
    float* __restrict__ C, long long ldc,
    int M, int N, int K)
{
    extern __shared__ __align__(16) char smem[];
    __nv_bfloat16* sAhi = (__nv_bfloat16*)smem;
    __nv_bfloat16* sAlo = sAhi + TILE_ELT;
    __nv_bfloat16* sBhi = sAlo + TILE_ELT;
    __nv_bfloat16* sBlo = sBhi + TILE_ELT;
    uint32_t aHiB = smem_u32(sAhi), aLoB = smem_u32(sAlo);
    uint32_t bHiB = smem_u32(sBhi), bLoB = smem_u32(sBlo);

    int tid = threadIdx.x, lane = tid & 31, wid = tid >> 5;
    int m0 = blockIdx.y * 128, n0 = blockIdx.x * 128;
    int wm = (wid & 1) * 64, wn = (wid >> 1) * 32;

    float acc[4][4][4];
#pragma unroll
    for (int i = 0; i < 4; i++)
#pragma unroll
        for (int j = 0; j < 4; j++)
#pragma unroll
            for (int q = 0; q < 4; q++) acc[i][j][q] = 0.f;

    int nChunks = (K + 63) / 64;
    for (int ch = 0; ch < nChunks; ch++) {
        int k0g = ch * 64;
        bool fullK = (k0g + 64 <= K);
        // ---- load + split-convert A tile (128 rows x 32 float2 slots) ----
        if (fullK && m0 + 128 <= M) {
#pragma unroll 4
            for (int it = 0; it < 16; it++) {
                int f = tid + it * 256;
                int row = f >> 5, k = (f & 31) * 2;
                float2 v = *(const float2*)(A + (long long)(m0 + row) * lda + (k0g + k));
                __nv_bfloat162 h2, l2; split_bf16x2(v, h2, l2);
                *(__nv_bfloat162*)&sAhi[row * STR + k] = h2;
                *(__nv_bfloat162*)&sAlo[row * STR + k] = l2;
            }
        } else {
#pragma unroll 4
            for (int it = 0; it < 16; it++) {
                int f = tid + it * 256;
                int row = f >> 5, k = (f & 31) * 2;
                long long m = m0 + row;
                int kg = k0g + k;
                float2 v = make_float2(0.f, 0.f);
                if (m < M && kg < K) {
                    if (kg + 1 < K) v = *(const float2*)(A + m * lda + kg);
                    else v.x = A[m * lda + kg];
                }
                __nv_bfloat162 h2, l2; split_bf16x2(v, h2, l2);
                *(__nv_bfloat162*)&sAhi[row * STR + k] = h2;
                *(__nv_bfloat162*)&sAlo[row * STR + k] = l2;
            }
        }
        // ---- load + split-convert B tile (128 rows x 32 float2 slots) ----
        if (fullK && n0 + 128 <= N) {
#pragma unroll 4
            for (int it = 0; it < 16; it++) {
                int f = tid + it * 256;
                int row = f >> 5, k = (f & 31) * 2;
                float2 v = *(const float2*)(B + (long long)(n0 + row) * ldb + (k0g + k));
                __nv_bfloat162 h2, l2; split_bf16x2(v, h2, l2);
                *(__nv_bfloat162*)&sBhi[row * STR + k] = h2;
                *(__nv_bfloat162*)&sBlo[row * STR + k] = l2;
            }
        } else {
#pragma unroll 4
            for (int it = 0; it < 16; it++) {
                int f = tid + it * 256;
                int row = f >> 5, k = (f & 31) * 2;
                long long n = n0 + row;
                int kg = k0g + k;
                float2 v = make_float2(0.f, 0.f);
                if (n < N && kg < K) {
                    if (kg + 1 < K) v = *(const float2*)(B + n * ldb + kg);
                    else v.x = B[n * ldb + kg];
                }
                __nv_bfloat162 h2, l2; split_bf16x2(v, h2, l2);
                *(__nv_bfloat162*)&sBhi[row * STR + k] = h2;
                *(__nv_bfloat162*)&sBlo[row * STR + k] = l2;
            }
        }
        __syncthreads();
        // ---- compute: 3 passes (hi*hi, hi*lo, lo*hi) ----
#pragma unroll
        for (int ks = 0; ks < 4; ks++) {
            int kk = ks * 16;
            uint32_t aF[4][4], bF[4][2];
            uint32_t aOff = (uint32_t)((wm + (lane & 15)) * STR + kk + ((lane >> 4) * 8)) * 2;
            uint32_t bOff = (uint32_t)((wn + (lane & 7)) * STR + kk + (((lane >> 3) & 1) * 8)) * 2;
            // A-hi x B-hi
#pragma unroll
            for (int mt = 0; mt < 4; mt++) ldm4(aF[mt], aHiB + aOff + mt * 16 * STR * 2);
#pragma unroll
            for (int nt = 0; nt < 4; nt++) ldm2(bF[nt], bHiB + bOff + nt * 8 * STR * 2);
#pragma unroll
            for (int mt = 0; mt < 4; mt++)
#pragma unroll
                for (int nt = 0; nt < 4; nt++) mma16816(acc[mt][nt], aF[mt], bF[nt]);
            // A-hi x B-lo
            {
                uint32_t bL[4][2];
#pragma unroll
                for (int nt = 0; nt < 4; nt++) ldm2(bL[nt], bLoB + bOff + nt * 8 * STR * 2);
#pragma unroll
                for (int mt = 0; mt < 4; mt++)
#pragma unroll
                    for (int nt = 0; nt < 4; nt++) mma16816(acc[mt][nt], aF[mt], bL[nt]);
            }
            // A-lo x B-hi
#pragma unroll
            for (int mt = 0; mt < 4; mt++) ldm4(aF[mt], aLoB + aOff + mt * 16 * STR * 2);
#pragma unroll
            for (int mt = 0; mt < 4; mt++)
#pragma unroll
                for (int nt = 0; nt < 4; nt++) mma16816(acc[mt][nt], aF[mt], bF[nt]);
        }
        __syncthreads();
    }
    // ---- epilogue ----
#pragma unroll
    for (int mt = 0; mt < 4; mt++) {
        long long r0 = m0 + wm + mt * 16 + (lane >> 2);
        long long r1 = r0 + 8;
#pragma unroll
        for (int nt = 0; nt < 4; nt++) {
            int c0 = n0 + wn + nt * 8 + (lane & 3) * 2;
            float b0v = 0.f, b1v = 0.f;
            if (bias) {
                if (c0 < N) b0v = bias[c0];
                if (c0 + 1 < N) b1v = bias[c0 + 1];
            }
            if (r0 < M) {
                if (c0 < N)     C[r0 * ldc + c0]     = acc[mt][nt][0] + b0v;
                if (c0 + 1 < N) C[r0 * ldc + c0 + 1] = acc[mt][nt][1] + b1v;
            }
            if (r1 < M) {
                if (c0 < N)     C[r1 * ldc + c0]     = acc[mt][nt][2] + b0v;
                if (c0 + 1 < N) C[r1 * ldc + c0 + 1] = acc[mt][nt][3] + b1v;
            }
        }
    }
}

// ---------------- skinny GEMM (M<=8), atomicAdd into C ----------------
#define SK_NT 32
#define SK_KC 1024
__global__ void __launch_bounds__(256) skinny_gemm_kernel(
    const float* __restrict__ A, long long sAm,
    const float* __restrict__ W, long long sWn,
    float* __restrict__ C, int M, int N, int K)
{
    __shared__ float As[8][SK_KC];
    int n0 = blockIdx.x * SK_NT;
    int k0 = blockIdx.y * SK_KC;
    int kLen = min(SK_KC, K - k0);
    int tid = threadIdx.x;
    for (int m = 0; m < M; m++)
        for (int k = tid; k < SK_KC; k += 256)
            As[m][k] = (k < kLen) ? A[(long long)m * sAm + k0 + k] : 0.f;
    __syncthreads();
    int warp = tid >> 5, lane = tid & 31;
    if (warp < M) {
        for (int nn = 0; nn < SK_NT; nn++) {
            int n = n0 + nn;
            if (n >= N) break;
            const float* wr = W + (long long)n * sWn + k0;
            float s = 0.f;
            for (int i = lane; i < kLen; i += 32) s += As[warp][i] * wr[i];
#pragma unroll
            for (int o = 16; o; o >>= 1) s += __shfl_xor_sync(0xffffffffu, s, o);
            if (lane == 0) atomicAdd(&C[warp * N + n], s);
        }
    }
}

// ---------------- transpose out_W [E,H] -> g_outWT [H,E] ----------------
__global__ void transpose_kernel(const float* __restrict__ src, float* __restrict__ dst)
{
    __shared__ float t[32][33];
    int r0 = blockIdx.y * 32, c0 = blockIdx.x * 32;
#pragma unroll
    for (int i = 0; i < 32; i += 8) {
        int r = r0 + threadIdx.y + i, c = c0 + threadIdx.x;
        if (r < EE && c < HH) t[threadIdx.y + i][threadIdx.x] = src[(long long)r * HH + c];
    }
    __syncthreads();
#pragma unroll
    for (int i = 0; i < 32; i += 8) {
        int rr = c0 + threadIdx.y + i, cc = r0 + threadIdx.x;
        if (rr < HH && cc < EE) dst[(long long)rr * EE + cc] = t[threadIdx.x][threadIdx.y + i];
    }
}

// ---------------- init / copy ----------------
__global__ void init_kernel(float* dst, const float* b1, const float* b2, int n, int period)
{
    int i = blockIdx.x * 256 + threadIdx.x;
    if (i < n) {
        float v = 0.f; int p = i % period;
        if (b1) v += b1[p];
        if (b2) v += b2[p];
        dst[i] = v;
    }
}
__global__ void copy_hfinal_kernel()
{
    int i = blockIdx.x * 256 + threadIdx.x;
    if (i < BB * HH) {
        int b = i / HH, j = i % HH;
        g_hA[i] = g_enc[(b * TT + TT - 1) * HH + j];
    }
}
__global__ void copy_emb0_kernel()
{
    int i = blockIdx.x * 256 + threadIdx.x;
    if (i < BB * HH) g_emb[i] = g_nemb[i];
}

// ---------------- encoder recurrent step ----------------
__global__ void __launch_bounds__(256) enc_step_kernel(const float* __restrict__ Whh, int t)
{
    const float* cIn  = (t & 1) ? g_cB : g_cA;
    float*       cOut = (t & 1) ? g_cA : g_cB;
    int warp = threadIdx.x >> 5, lane = threadIdx.x & 31;
    int j = blockIdx.x * 8 + warp;
    int gate = lane >> 3, b = lane & 7;
    float acc = 0.f;
    if (t > 0) {
        const float* hr = g_enc + (long long)(b * TT + t - 1) * HH;
        const float* wr = Whh + (long long)(gate * HH + j) * HH;
        float a0=0,a1=0,a2=0,a3=0;
#pragma unroll 2
        for (int k = 0; k < HH; k += 4) {
            a0 += hr[k]*wr[k]; a1 += hr[k+1]*wr[k+1];
            a2 += hr[k+2]*wr[k+2]; a3 += hr[k+3]*wr[k+3];
        }
        acc = (a0+a1)+(a2+a3);
    }
    float gv = g_preg[(long long)(b * TT + t) * G4H + gate * HH + j] + acc;
    const unsigned F = 0xffffffffu;
    float gi = __shfl_sync(F, gv, b);
    float gf = __shfl_sync(F, gv, 8 + b);
    float gg = __shfl_sync(F, gv, 16 + b);
    float go = __shfl_sync(F, gv, 24 + b);
    if (gate == 0) {
        float c = sigmoidf_(gf) * cIn[b * HH + j] + sigmoidf_(gi) * tanhf(gg);
        cOut[b * HH + j] = c;
        g_enc[(long long)(b * TT + t) * HH + j] = sigmoidf_(go) * tanhf(c);
    }
}

// ---------------- decoder attention (block per b) ----------------
__global__ void __launch_bounds__(256) dec_attn_kernel(const float* __restrict__ attnW, int s)
{
    const float* hIn = (s & 1) ? g_hB : g_hA;
    __shared__ float sx[2 * HH];
    __shared__ float red[256];
    __shared__ float saw[TT];
    __shared__ float sval;
    int b = blockIdx.x, tid = threadIdx.x;
    for (int k = tid; k < HH; k += 256) {
        sx[k] = g_emb[b * HH + k];
        sx[HH + k] = hIn[b * HH + k];
    }
    __syncthreads();
    int t = tid & 127, half = tid >> 7;
    {
        const float* wr = attnW + (long long)t * (3 * HH) + half * HH;
        const float* xr = sx + half * HH;
        float a0=0,a1=0,a2=0,a3=0;
#pragma unroll 2
        for (int k = 0; k < HH; k += 4) {
            a0 += xr[k]*wr[k]; a1 += xr[k+1]*wr[k+1];
            a2 += xr[k+2]*wr[k+2]; a3 += xr[k+3]*wr[k+3];
        }
        red[tid] = (a0+a1)+(a2+a3);
    }
    __syncthreads();
    if (tid < 128) {
        float l = red[tid] + red[tid + 128] + g_n2l[(s * BB + b) * TT + tid];
        saw[tid] = l; red[tid] = l;
    }
    __syncthreads();
    for (int o = 64; o > 0; o >>= 1) {
        if (tid < o) red[tid] = fmaxf(red[tid], red[tid + o]);
        __syncthreads();
    }
    if (tid == 0) sval = red[0];
    __syncthreads();
    float mx = sval;
    if (tid < 128) { float e = expf(saw[tid] - mx); saw[tid] = e; red[tid] = e; }
    __syncthreads();
    for (int o = 64; o > 0; o >>= 1) {
        if (tid < o) red[tid] += red[tid + o];
        __syncthreads();
    }
    if (tid == 0) sval = red[0];
    __syncthreads();
    float inv = 1.f / sval;
    for (int j = tid; j < HH; j += 256) {
        const float* ep = g_enc + (long long)(b * TT) * HH + j;
        float acc = 0.f;
#pragma unroll 4
        for (int tt = 0; tt < TT; tt++) acc += saw[tt] * ep[(long long)tt * HH];
        g_applied[b * HH + j] = acc * inv;
    }
}

// ---------------- combine + relu ----------------
__global__ void __launch_bounds__(256) dec_comb_kernel(
    const float* __restrict__ combW, const float* __restrict__ combB)
{
    int warp = threadIdx.x >> 5, lane = threadIdx.x & 31;
    int j = blockIdx.x * 8 + warp;
    int b = lane & 7, ch = lane >> 3;
    const float* wr = combW + (long long)j * (2 * HH);
    const float* xe = g_emb + b * HH;
    const float* xa = g_applied + b * HH;
    float s0 = 0.f, s1 = 0.f;
#pragma unroll 2
    for (int i = 0; i < 250; i++) {
        int k = ch + 4 * i;
        s0 += xe[k] * wr[k];
        s1 += xa[k] * wr[HH + k];
    }
    float s = s0 + s1;
    s += __shfl_xor_sync(0xffffffffu, s, 8);
    s += __shfl_xor_sync(0xffffffffu, s, 16);
    if (ch == 0) g_comb[b * HH + j] = fmaxf(s + combB[j], 0.f);
}

// ---------------- decoder LSTM step ----------------
__global__ void __launch_bounds__(256) dec_lstm_kernel(
    const float* __restrict__ Wih, const float* __restrict__ Whh,
    const float* __restrict__ bih, const float* __restrict__ bhh, int s)
{
    const float* hIn  = (s & 1) ? g_hB : g_hA;
    const float* cIn  = (s & 1) ? g_cB : g_cA;
    float*       hOut = (s & 1) ? g_hA : g_hB;
    float*       cOut = (s & 1) ? g_cA : g_cB;
    int warp = threadIdx.x >> 5, lane = threadIdx.x & 31;
    int j = blockIdx.x * 8 + warp;
    int gate = lane >> 3, b = lane & 7;
    int row = gate * HH + j;
    const float* w1 = Wih + (long long)row * HH;
    const float* w2 = Whh + (long long)row * HH;
    const float* x1 = g_comb + b * HH;
    const float* x2 = hIn + b * HH;
    float a0=0,a1=0,a2=0,a3=0;
#pragma unroll 2
    for (int k = 0; k < HH; k += 4) {
        a0 += x1[k]*w1[k] + x2[k]*w2[k];
        a1 += x1[k+1]*w1[k+1] + x2[k+1]*w2[k+1];
        a2 += x1[k+2]*w1[k+2] + x2[k+2]*w2[k+2];
        a3 += x1[k+3]*w1[k+3] + x2[k+3]*w2[k+3];
    }
    float gv = (a0+a1)+(a2+a3) + bih[row] + bhh[row];
    const unsigned F = 0xffffffffu;
    float gi = __shfl_sync(F, gv, b);
    float gf = __shfl_sync(F, gv, 8 + b);
    float gg = __shfl_sync(F, gv, 16 + b);
    float go = __shfl_sync(F, gv, 24 + b);
    if (gate == 0) {
        float c = sigmoidf_(gf) * cIn[b * HH + j] + sigmoidf_(gi) * tanhf(gg);
        float h = sigmoidf_(go) * tanhf(c);
        cOut[b * HH + j] = c;
        hOut[b * HH + j] = h;
        g_Hs[(long long)(s * BB + b) * HH + j] = h;
    }
}

// ---------------- next-step emb via fused Mt ----------------
__global__ void __launch_bounds__(256) dec_embnext_kernel(int s, int snext)
{
    const float* hNew = (s & 1) ? g_hA : g_hB;
    int warp = threadIdx.x >> 5, lane = threadIdx.x & 31;
    int j = blockIdx.x * 8 + warp;
    int b = lane & 7, ch = lane >> 3;
    const float* mr = g_Mt + (long long)j * HH;
    const float* hr = hNew + b * HH;
    float s0 = 0.f;
#pragma unroll 2
    for (int i = 0; i < 250; i++) {
        int k = ch + 4 * i;
        s0 += hr[k] * mr[k];
    }
    s0 += __shfl_xor_sync(0xffffffffu, s0, 8);
    s0 += __shfl_xor_sync(0xffffffffu, s0, 16);
    if (ch == 0)
        g_emb[b * HH + j] = s0 + g_bias2[j] + g_nemb[(long long)(snext * BB + b) * HH + j];
}

// ---------------- launcher ----------------
static void launch_mma(const float* A, long long lda, const float* B, long long ldb,
                       const float* bias, float* C, long long ldc, int M, int N, int K)
{
    dim3 g((N + 127) / 128, (M + 127) / 128);
    mma_gemm<<<g, 256, MMA_SMEM>>>(A, lda, B, ldb, bias, C, ldc, M, N, K);
}

extern "C" void kernel_launch(void* const* d_in, const int* in_sizes, int n_in,
                              void* d_out, int out_size)
{
    const float* input    = (const float*)d_in[0];
    const float* noise1   = (const float*)d_in[2];
    const float* noise2   = (const float*)d_in[3];
    const float* init_dec = (const float*)d_in[4];
    const float* eWih = (const float*)d_in[5];
    const float* eWhh = (const float*)d_in[6];
    const float* ebih = (const float*)d_in[7];
    const float* ebhh = (const float*)d_in[8];
    const float* dWih = (const float*)d_in[9];
    const float* dWhh = (const float*)d_in[10];
    const float* dbih = (const float*)d_in[11];
    const float* dbhh = (const float*)d_in[12];
    const float* embW = (const float*)d_in[13];
    const float* embb = (const float*)d_in[14];
    const float* attW = (const float*)d_in[15];
    const float* attb = (const float*)d_in[16];
    const float* combW = (const float*)d_in[17];
    const float* combb = (const float*)d_in[18];
    const float* outW = (const float*)d_in[19];
    const float* outb = (const float*)d_in[20];
    float* out = (float*)d_out;

    cudaFuncSetAttribute(mma_gemm, cudaFuncAttributeMaxDynamicSharedMemorySize, MMA_SMEM);

    float *preg, *Mt, *nemb, *n2l, *bias2, *bias4h, *emb, *Hs, *cA, *outWT;
    cudaGetSymbolAddress((void**)&preg,   g_preg);
    cudaGetSymbolAddress((void**)&Mt,     g_Mt);
    cudaGetSymbolAddress((void**)&nemb,   g_nemb);
    cudaGetSymbolAddress((void**)&n2l,    g_n2l);
    cudaGetSymbolAddress((void**)&bias2,  g_bias2);
    cudaGetSymbolAddress((void**)&bias4h, g_bias4h);
    cudaGetSymbolAddress((void**)&emb,    g_emb);
    cudaGetSymbolAddress((void**)&Hs,     g_Hs);
    cudaGetSymbolAddress((void**)&cA,     g_cA);
    cudaGetSymbolAddress((void**)&outWT,  g_outWT);

    // small inits
    init_kernel<<<(BB*HH + 255) / 256, 256>>>(cA, nullptr, nullptr, BB*HH, 1);
    init_kernel<<<(G4H + 255) / 256, 256>>>(bias4h, ebih, ebhh, G4H, G4H);
    init_kernel<<<(HH + 255) / 256, 256>>>(bias2, nullptr, nullptr, HH, 1);

    // transpose out_W -> [H, E]
    transpose_kernel<<<dim3((HH + 31) / 32, (EE + 31) / 32), dim3(32, 8)>>>(outW, outWT);

    // big GEMMs on tensor cores (split-bf16 3-pass, direct write + bias)
    launch_mma(input, EE, eWih, EE, bias4h, preg, G4H, BB*TT, G4H, EE);
    launch_mma(embW, EN, outWT, EE, nullptr, Mt, HH, HH, HH, EE);
    launch_mma(noise1, NZ, embW + EE, EN, embb, nemb, HH, SS*BB, HH, NZ);
    launch_mma(noise2, HH, attW + 2*HH, 3*HH, attb, n2l, TT, SS*BB, TT, HH);

    // bias2 = emb_W_E @ out_b (skinny fp32)
    skinny_gemm_kernel<<<dim3(32, 30), 256>>>(outb, 0, embW, EN, bias2, 1, HH, EE);

    // encoder recurrence
    for (int t = 0; t < TT; t++)
        enc_step_kernel<<<125, 256>>>(eWhh, t);
    copy_hfinal_kernel<<<(BB*HH + 255) / 256, 256>>>();

    // decoder step-0 emb
    copy_emb0_kernel<<<(BB*HH + 255) / 256, 256>>>();
    skinny_gemm_kernel<<<dim3(32, 30), 256>>>(init_dec, EE, embW, EN, emb, BB, HH, EE);

    for (int s = 0; s < SS; s++) {
        dec_attn_kernel<<<BB, 256>>>(attW, s);
        dec_comb_kernel<<<125, 256>>>(combW, combb);
        dec_lstm_kernel<<<125, 256>>>(dWih, dWhh, dbih, dbhh, s);
        if (s + 1 < SS) dec_embnext_kernel<<<125, 256>>>(s, s + 1);
    }

    // summary = Hs @ out_W.T + out_b  (tensor cores)
    launch_mma(Hs, HH, outW, HH, outb, out, EE, SS*BB, EE, HH);
}

// round 12
// speedup vs baseline: 1.4639x; 1.0513x over previous
#include <cuda_runtime.h>
#include <cuda_bf16.h>
#include <cstdint>

#define BB   8
#define TT   128
#define EE   30522
#define HH   1000
#define SS   64
#define NZ   10000
#define EN   40522   // E + NZ
#define G4H  4000    // 4*H

// ---------------- static scratch ----------------
__device__ float g_preg[BB*TT*G4H];
__device__ float g_enc [BB*TT*HH];
__device__ float g_nemb[SS*BB*HH];
__device__ float g_n2l [SS*BB*TT];
__device__ float g_Mt  [HH*HH];
__device__ float g_bias2[HH];
__device__ float g_emb [BB*HH];
__device__ float g_applied[BB*HH];
__device__ float g_comb[BB*HH];
__device__ __align__(16) float g_Hs[SS*BB*HH];
__device__ __align__(16) float g_outWT[HH*EE];   // out_W transposed: [H, E]
__device__ float g_cA[BB*HH], g_cB[BB*HH];
__device__ float g_hA[BB*HH], g_hB[BB*HH];

__device__ __forceinline__ float sigmoidf_(float x) { return 1.f / (1.f + expf(-x)); }

// guarded load of 4 consecutive floats (k element-offset is even -> float2 8B aligned)
__device__ __forceinline__ void ld4(const float* __restrict__ p, int k, int kEnd,
                                    bool rowOk, float* r)
{
    if (rowOk && k + 3 < kEnd) {
        float2 u = *(const float2*)(p + k);
        float2 v = *(const float2*)(p + k + 2);
        r[0] = u.x; r[1] = u.y; r[2] = v.x; r[3] = v.y;
    } else {
#pragma unroll
        for (int i = 0; i < 4; i++)
            r[i] = (rowOk && k + i < kEnd) ? p[k + i] : 0.f;
    }
}

// ================= tuned fp32 SGEMM (double-buffered, k-split) =============
// C[m*ldc+n] += sum_k A[m*lda+k] * B[n*ldb+k]   (C pre-initialized with bias)
#define BM 128
#define BN 128
#define BK 8

__global__ void __launch_bounds__(256, 2) sgemm(
    const float* __restrict__ A, long long lda,
    const float* __restrict__ B, long long ldb,
    float* __restrict__ C, long long ldc,
    int M, int N, int K, int kChunk)
{
    __shared__ float As[2][BK][BM];
    __shared__ float Ws[2][BK][BN];
    int tid = threadIdx.x;
    int m0 = blockIdx.y * BM, n0 = blockIdx.x * BN;
    int kBeg = blockIdx.z * kChunk;
    int kEnd = min(K, kBeg + kChunk);
    if (kBeg >= kEnd) return;

    int ldRow = tid >> 1;           // 0..127
    int ldK   = (tid & 1) * 4;      // 0 or 4
    long long aRow = m0 + ldRow;
    long long bRow = n0 + ldRow;
    const float* Ap = A + aRow * lda;
    const float* Bp = B + bRow * ldb;
    bool aOk = aRow < M;
    bool bOk = bRow < N;

    int tr = tid >> 4, tc = tid & 15;
    float acc[8][8];
#pragma unroll
    for (int i = 0; i < 8; i++)
#pragma unroll
        for (int j = 0; j < 8; j++) acc[i][j] = 0.f;

    float pa[4], pb[4];
    // stage 0
    ld4(Ap, kBeg + ldK, kEnd, aOk, pa);
    ld4(Bp, kBeg + ldK, kEnd, bOk, pb);
#pragma unroll
    for (int i = 0; i < 4; i++) {
        As[0][ldK + i][ldRow] = pa[i];
        Ws[0][ldK + i][ldRow] = pb[i];
    }
    __syncthreads();

    int cur = 0;
    for (int k0 = kBeg; k0 < kEnd; k0 += BK) {
        bool hasNext = (k0 + BK) < kEnd;
        if (hasNext) {
            ld4(Ap, k0 + BK + ldK, kEnd, aOk, pa);
            ld4(Bp, k0 + BK + ldK, kEnd, bOk, pb);
        }
        // compute on current stage
#pragma unroll
        for (int kk = 0; kk < BK; kk++) {
            float4 x0 = *(const float4*)&As[cur][kk][tr * 4];
            float4 x1 = *(const float4*)&As[cur][kk][64 + tr * 4];
            float4 y0 = *(const float4*)&Ws[cur][kk][tc * 4];
            float4 y1 = *(const float4*)&Ws[cur][kk][64 + tc * 4];
            float aF[8] = {x0.x,x0.y,x0.z,x0.w,x1.x,x1.y,x1.z,x1.w};
            float wF[8] = {y0.x,y0.y,y0.z,y0.w,y1.x,y1.y,y1.z,y1.w};
#pragma unroll
            for (int i = 0; i < 8; i++)
#pragma unroll
                for (int j = 0; j < 8; j++)
                    acc[i][j] += aF[i] * wF[j];
        }
        if (hasNext) {
            int nxt = cur ^ 1;
#pragma unroll
            for (int i = 0; i < 4; i++) {
                As[nxt][ldK + i][ldRow] = pa[i];
                Ws[nxt][ldK + i][ldRow] = pb[i];
            }
        }
        __syncthreads();
        cur ^= 1;
    }
    // epilogue: accumulate into pre-initialized C
#pragma unroll
    for (int i = 0; i < 8; i++) {
        int mloc = (i < 4) ? (tr * 4 + i) : (64 + tr * 4 + i - 4);
        long long m = m0 + mloc;
        if (m >= M) continue;
#pragma unroll
        for (int j = 0; j < 8; j++) {
            int nloc = (j < 4) ? (tc * 4 + j) : (64 + tc * 4 + j - 4);
            int n = n0 + nloc;
            if (n >= N) continue;
            atomicAdd(&C[m * ldc + n], acc[i][j]);
        }
    }
}

// ---------------- skinny GEMM (M<=8), atomicAdd into C ----------------
#define SK_NT 32
#define SK_KC 1024
__global__ void __launch_bounds__(256) skinny_gemm_kernel(
    const float* __restrict__ A, long long sAm,
    const float* __restrict__ W, long long sWn,
    float* __restrict__ C, int M, int N, int K)
{
    __shared__ float As[8][SK_KC];
    int n0 = blockIdx.x * SK_NT;
    int k0 = blockIdx.y * SK_KC;
    int kLen = min(SK_KC, K - k0);
    int tid = threadIdx.x;
    for (int m = 0; m < M; m++)
        for (int k = tid; k < SK_KC; k += 256)
            As[m][k] = (k < kLen) ? A[(long long)m * sAm + k0 + k] : 0.f;
    __syncthreads();
    int warp = tid >> 5, lane = tid & 31;
    if (warp < M) {
        for (int nn = 0; nn < SK_NT; nn++) {
            int n = n0 + nn;
            if (n >= N) break;
            const float* wr = W + (long long)n * sWn + k0;
            float s = 0.f;
            for (int i = lane; i < kLen; i += 32) s += As[warp][i] * wr[i];
#pragma unroll
            for (int o = 16; o; o >>= 1) s += __shfl_xor_sync(0xffffffffu, s, o);
            if (lane == 0) atomicAdd(&C[warp * N + n], s);
        }
    }
}

// ---------------- transpose out_W [E,H] -> g_outWT [H,E] ----------------
__global__ void transpose_kernel(const float* __restrict__ src, float* __restrict__ dst)
{
    __shared__ float t[32][33];
    int r0 = blockIdx.y * 32, c0 = blockIdx.x * 32;
#pragma unroll
    for (int i = 0; i < 32; i += 8) {
        int r = r0 + threadIdx.y + i, c = c0 + threadIdx.x;
        if (r < EE && c < HH) t[threadIdx.y + i][threadIdx.x] = src[(long long)r * HH + c];
    }
    __syncthreads();
#pragma unroll
    for (int i = 0; i < 32; i += 8) {
        int rr = c0 + threadIdx.y + i, cc = r0 + threadIdx.x;
        if (rr < HH && cc < EE) dst[(long long)rr * EE + cc] = t[threadIdx.x][threadIdx.y + i];
    }
}

// ---------------- init / copy ----------------
__global__ void init_kernel(float* dst, const float* b1, const float* b2, int n, int period)
{
    int i = blockIdx.x * 256 + threadIdx.x;
    if (i < n) {
        float v = 0.f; int p = i % period;
        if (b1) v += b1[p];
        if (b2) v += b2[p];
        dst[i] = v;
    }
}
__global__ void copy_hfinal_kernel()
{
    int i = blockIdx.x * 256 + threadIdx.x;
    if (i < BB * HH) {
        int b = i / HH, j = i % HH;
        g_hA[i] = g_enc[(b * TT + TT - 1) * HH + j];
    }
}
__global__ void copy_emb0_kernel()
{
    int i = blockIdx.x * 256 + threadIdx.x;
    if (i < BB * HH) g_emb[i] = g_nemb[i];
}

// ---------------- encoder recurrent step ----------------
__global__ void __launch_bounds__(256) enc_step_kernel(const float* __restrict__ Whh, int t)
{
    const float* cIn  = (t & 1) ? g_cB : g_cA;
    float*       cOut = (t & 1) ? g_cA : g_cB;
    int warp = threadIdx.x >> 5, lane = threadIdx.x & 31;
    int j = blockIdx.x * 8 + warp;
    int gate = lane >> 3, b = lane & 7;
    float acc = 0.f;
    if (t > 0) {
        const float* hr = g_enc + (long long)(b * TT + t - 1) * HH;
        const float* wr = Whh + (long long)(gate * HH + j) * HH;
        float a0=0,a1=0,a2=0,a3=0;
#pragma unroll 2
        for (int k = 0; k < HH; k += 4) {
            a0 += hr[k]*wr[k]; a1 += hr[k+1]*wr[k+1];
            a2 += hr[k+2]*wr[k+2]; a3 += hr[k+3]*wr[k+3];
        }
        acc = (a0+a1)+(a2+a3);
    }
    float gv = g_preg[(long long)(b * TT + t) * G4H + gate * HH + j] + acc;
    const unsigned F = 0xffffffffu;
    float gi = __shfl_sync(F, gv, b);
    float gf = __shfl_sync(F, gv, 8 + b);
    float gg = __shfl_sync(F, gv, 16 + b);
    float go = __shfl_sync(F, gv, 24 + b);
    if (gate == 0) {
        float c = sigmoidf_(gf) * cIn[b * HH + j] + sigmoidf_(gi) * tanhf(gg);
        cOut[b * HH + j] = c;
        g_enc[(long long)(b * TT + t) * HH + j] = sigmoidf_(go) * tanhf(c);
    }
}

// ---------------- decoder attention (block per b) ----------------
__global__ void __launch_bounds__(256) dec_attn_kernel(const float* __restrict__ attnW, int s)
{
    const float* hIn = (s & 1) ? g_hB : g_hA;
    __shared__ float sx[2 * HH];
    __shared__ float red[256];
    __shared__ float saw[TT];
    __shared__ float sval;
    int b = blockIdx.x, tid = threadIdx.x;
    for (int k = tid; k < HH; k += 256) {
        sx[k] = g_emb[b * HH + k];
        sx[HH + k] = hIn[b * HH + k];
    }
    __syncthreads();
    int t = tid & 127, half = tid >> 7;
    {
        const float* wr = attnW + (long long)t * (3 * HH) + half * HH;
        const float* xr = sx + half * HH;
        float a0=0,a1=0,a2=0,a3=0;
#pragma unroll 2
        for (int k = 0; k < HH; k += 4) {
            a0 += xr[k]*wr[k]; a1 += xr[k+1]*wr[k+1];
            a2 += xr[k+2]*wr[k+2]; a3 += xr[k+3]*wr[k+3];
        }
        red[tid] = (a0+a1)+(a2+a3);
    }
    __syncthreads();
    if (tid < 128) {
        float l = red[tid] + red[tid + 128] + g_n2l[(s * BB + b) * TT + tid];
        saw[tid] = l; red[tid] = l;
    }
    __syncthreads();
    for (int o = 64; o > 0; o >>= 1) {
        if (tid < o) red[tid] = fmaxf(red[tid], red[tid + o]);
        __syncthreads();
    }
    if (tid == 0) sval = red[0];
    __syncthreads();
    float mx = sval;
    if (tid < 128) { float e = expf(saw[tid] - mx); saw[tid] = e; red[tid] = e; }
    __syncthreads();
    for (int o = 64; o > 0; o >>= 1) {
        if (tid < o) red[tid] += red[tid + o];
        __syncthreads();
    }
    if (tid == 0) sval = red[0];
    __syncthreads();
    float inv = 1.f / sval;
    for (int j = tid; j < HH; j += 256) {
        const float* ep = g_enc + (long long)(b * TT) * HH + j;
        float acc = 0.f;
#pragma unroll 4
        for (int tt = 0; tt < TT; tt++) acc += saw[tt] * ep[(long long)tt * HH];
        g_applied[b * HH + j] = acc * inv;
    }
}

// ---------------- combine + relu ----------------
__global__ void __launch_bounds__(256) dec_comb_kernel(
    const float* __restrict__ combW, const float* __restrict__ combB)
{
    int warp = threadIdx.x >> 5, lane = threadIdx.x & 31;
    int j = blockIdx.x * 8 + warp;
    int b = lane & 7, ch = lane >> 3;
    const float* wr = combW + (long long)j * (2 * HH);
    const float* xe = g_emb + b * HH;
    const float* xa = g_applied + b * HH;
    float s0 = 0.f, s1 = 0.f;
#pragma unroll 2
    for (int i = 0; i < 250; i++) {
        int k = ch + 4 * i;
        s0 += xe[k] * wr[k];
        s1 += xa[k] * wr[HH + k];
    }
    float s = s0 + s1;
    s += __shfl_xor_sync(0xffffffffu, s, 8);
    s += __shfl_xor_sync(0xffffffffu, s, 16);
    if (ch == 0) g_comb[b * HH + j] = fmaxf(s + combB[j], 0.f);
}

// ---------------- decoder LSTM step ----------------
__global__ void __launch_bounds__(256) dec_lstm_kernel(
    const float* __restrict__ Wih, const float* __restrict__ Whh,
    const float* __restrict__ bih, const float* __restrict__ bhh, int s)
{
    const float* hIn  = (s & 1) ? g_hB : g_hA;
    const float* cIn  = (s & 1) ? g_cB : g_cA;
    float*       hOut = (s & 1) ? g_hA : g_hB;
    float*       cOut = (s & 1) ? g_cA : g_cB;
    int warp = threadIdx.x >> 5, lane = threadIdx.x & 31;
    int j = blockIdx.x * 8 + warp;
    int gate = lane >> 3, b = lane & 7;
    int row = gate * HH + j;
    const float* w1 = Wih + (long long)row * HH;
    const float* w2 = Whh + (long long)row * HH;
    const float* x1 = g_comb + b * HH;
    const float* x2 = hIn + b * HH;
    float a0=0,a1=0,a2=0,a3=0;
#pragma unroll 2
    for (int k = 0; k < HH; k += 4) {
        a0 += x1[k]*w1[k] + x2[k]*w2[k];
        a1 += x1[k+1]*w1[k+1] + x2[k+1]*w2[k+1];
        a2 += x1[k+2]*w1[k+2] + x2[k+2]*w2[k+2];
        a3 += x1[k+3]*w1[k+3] + x2[k+3]*w2[k+3];
    }
    float gv = (a0+a1)+(a2+a3) + bih[row] + bhh[row];
    const unsigned F = 0xffffffffu;
    float gi = __shfl_sync(F, gv, b);
    float gf = __shfl_sync(F, gv, 8 + b);
    float gg = __shfl_sync(F, gv, 16 + b);
    float go = __shfl_sync(F, gv, 24 + b);
    if (gate == 0) {
        float c = sigmoidf_(gf) * cIn[b * HH + j] + sigmoidf_(gi) * tanhf(gg);
        float h = sigmoidf_(go) * tanhf(c);
        cOut[b * HH + j] = c;
        hOut[b * HH + j] = h;
        g_Hs[(long long)(s * BB + b) * HH + j] = h;
    }
}

// ---------------- next-step emb via fused Mt ----------------
__global__ void __launch_bounds__(256) dec_embnext_kernel(int s, int snext)
{
    const float* hNew = (s & 1) ? g_hA : g_hB;
    int warp = threadIdx.x >> 5, lane = threadIdx.x & 31;
    int j = blockIdx.x * 8 + warp;
    int b = lane & 7, ch = lane >> 3;
    const float* mr = g_Mt + (long long)j * HH;
    const float* hr = hNew + b * HH;
    float s0 = 0.f;
#pragma unroll 2
    for (int i = 0; i < 250; i++) {
        int k = ch + 4 * i;
        s0 += hr[k] * mr[k];
    }
    s0 += __shfl_xor_sync(0xffffffffu, s0, 8);
    s0 += __shfl_xor_sync(0xffffffffu, s0, 16);
    if (ch == 0)
        g_emb[b * HH + j] = s0 + g_bias2[j] + g_nemb[(long long)(snext * BB + b) * HH + j];
}

// ---------------- launcher ----------------
extern "C" void kernel_launch(void* const* d_in, const int* in_sizes, int n_in,
                              void* d_out, int out_size)
{
    const float* input    = (const float*)d_in[0];
    const float* noise1   = (const float*)d_in[2];
    const float* noise2   = (const float*)d_in[3];
    const float* init_dec = (const float*)d_in[4];
    const float* eWih = (const float*)d_in[5];
    const float* eWhh = (const float*)d_in[6];
    const float* ebih = (const float*)d_in[7];
    const float* ebhh = (const float*)d_in[8];
    const float* dWih = (const float*)d_in[9];
    const float* dWhh = (const float*)d_in[10];
    const float* dbih = (const float*)d_in[11];
    const float* dbhh = (const float*)d_in[12];
    const float* embW = (const float*)d_in[13];
    const float* embb = (const float*)d_in[14];
    const float* attW = (const float*)d_in[15];
    const float* attb = (const float*)d_in[16];
    const float* combW = (const float*)d_in[17];
    const float* combb = (const float*)d_in[18];
    const float* outW = (const float*)d_in[19];
    const float* outb = (const float*)d_in[20];
    float* out = (float*)d_out;

    float *preg, *Mt, *nemb, *n2l, *bias2, *emb, *Hs, *cA, *outWT;
    cudaGetSymbolAddress((void**)&preg,   g_preg);
    cudaGetSymbolAddress((void**)&Mt,     g_Mt);
    cudaGetSymbolAddress((void**)&nemb,   g_nemb);
    cudaGetSymbolAddress((void**)&n2l,    g_n2l);
    cudaGetSymbolAddress((void**)&bias2,  g_bias2);
    cudaGetSymbolAddress((void**)&emb,    g_emb);
    cudaGetSymbolAddress((void**)&Hs,     g_Hs);
    cudaGetSymbolAddress((void**)&cA,     g_cA);
    cudaGetSymbolAddress((void**)&outWT,  g_outWT);

    // launch order arranged so ncu (-s 5 -c 1) captures sgemm(preg) at index 5
    init_kernel<<<(BB*TT*G4H + 255) / 256, 256>>>(preg, ebih, ebhh, BB*TT*G4H, G4H); // 0
    init_kernel<<<(BB*HH + 255) / 256, 256>>>(cA, nullptr, nullptr, BB*HH, 1);       // 1
    init_kernel<<<(HH + 255) / 256, 256>>>(bias2, nullptr, nullptr, HH, 1);          // 2
    transpose_kernel<<<dim3((HH + 31) / 32, (EE + 31) / 32), dim3(32, 8)>>>(outW, outWT); // 3
    init_kernel<<<(HH*HH + 255) / 256, 256>>>(Mt, nullptr, nullptr, HH*HH, 1);       // 4

    // 5: big one — preg = input @ eWih^T (+biases already in C)
    sgemm<<<dim3(32, 8, 2), 256>>>(input, EE, eWih, EE, preg, G4H,
                                   BB*TT, G4H, EE, 15264);

    init_kernel<<<(SS*BB*HH + 255) / 256, 256>>>(nemb, embb, nullptr, SS*BB*HH, HH);
    init_kernel<<<(SS*BB*TT + 255) / 256, 256>>>(n2l, attb, nullptr, SS*BB*TT, TT);
    init_kernel<<<(SS*BB*EE + 255) / 256, 256>>>(out, outb, nullptr, SS*BB*EE, EE);

    // Mt = embW_E @ outWT^T (k-contiguous both sides)
    sgemm<<<dim3(8, 8, 8), 256>>>(embW, EN, outWT, EE, Mt, HH,
                                  HH, HH, EE, 3816);
    // nemb += noise1 @ embW_nz^T
    sgemm<<<dim3(8, 4, 8), 256>>>(noise1, NZ, embW + EE, EN, nemb, HH,
                                  SS*BB, HH, NZ, 1256);
    // n2l += noise2 @ attW[:,2H:]^T
    sgemm<<<dim3(1, 4, 8), 256>>>(noise2, HH, attW + 2*HH, 3*HH, n2l, TT,
                                  SS*BB, TT, HH, 128);

    // bias2 = emb_W_E @ out_b (skinny fp32)
    skinny_gemm_kernel<<<dim3(32, 30), 256>>>(outb, 0, embW, EN, bias2, 1, HH, EE);

    // encoder recurrence
    for (int t = 0; t < TT; t++)
        enc_step_kernel<<<125, 256>>>(eWhh, t);
    copy_hfinal_kernel<<<(BB*HH + 255) / 256, 256>>>();

    // decoder step-0 emb
    copy_emb0_kernel<<<(BB*HH + 255) / 256, 256>>>();
    skinny_gemm_kernel<<<dim3(32, 30), 256>>>(init_dec, EE, embW, EN, emb, BB, HH, EE);

    for (int s = 0; s < SS; s++) {
        dec_attn_kernel<<<BB, 256>>>(attW, s);
        dec_comb_kernel<<<125, 256>>>(combW, combb);
        dec_lstm_kernel<<<125, 256>>>(dWih, dWhh, dbih, dbhh, s);
        if (s + 1 < SS) dec_embnext_kernel<<<125, 256>>>(s, s + 1);
    }

    // out += Hs @ out_W^T  (out pre-initialized with outb)
    sgemm<<<dim3(239, 4, 1), 256>>>(Hs, HH, outW, HH, out, EE,
                                    SS*BB, EE, HH, 1000);
}

// round 13
// speedup vs baseline: 2.0140x; 1.3758x over previous
#include <cuda_runtime.h>
#include <cuda_bf16.h>
#include <cstdint>

#define BB   8
#define TT   128
#define EE   30522
#define HH   1000
#define SS   64
#define NZ   10000
#define EN   40522   // E + NZ
#define G4H  4000    // 4*H

// ---------------- static scratch (16B-aligned for float4 row loads) --------
__device__ __align__(16) float g_preg[BB*TT*G4H];
__device__ __align__(16) float g_enc [BB*TT*HH];
__device__ __align__(16) float g_nemb[SS*BB*HH];
__device__ __align__(16) float g_n2l [SS*BB*TT];
__device__ __align__(16) float g_Mt  [HH*HH];
__device__ __align__(16) float g_bias2[HH];
__device__ __align__(16) float g_emb [BB*HH];
__device__ __align__(16) float g_applied[BB*HH];
__device__ __align__(16) float g_comb[BB*HH];
__device__ __align__(16) float g_Hs[SS*BB*HH];
__device__ __align__(16) float g_outWT[HH*EE];   // out_W transposed: [H, E]
__device__ __align__(16) float g_cA[BB*HH], g_cB[BB*HH];
__device__ __align__(16) float g_hA[BB*HH], g_hB[BB*HH];

__device__ __forceinline__ float sigmoidf_(float x) { return 1.f / (1.f + expf(-x)); }
__device__ __forceinline__ float dot4_(float4 a, float4 b) {
    return a.x*b.x + a.y*b.y + a.z*b.z + a.w*b.w;
}

// guarded load of 4 consecutive floats (k element-offset always EVEN -> 8B aligned)
__device__ __forceinline__ void ld4(const float* __restrict__ p, int k, int kEnd,
                                    bool rowOk, float* r)
{
    if (rowOk && k + 3 < kEnd) {
        float2 u = *(const float2*)(p + k);
        float2 v = *(const float2*)(p + k + 2);
        r[0] = u.x; r[1] = u.y; r[2] = v.x; r[3] = v.y;
    } else {
#pragma unroll
        for (int i = 0; i < 4; i++)
            r[i] = (rowOk && k + i < kEnd) ? p[k + i] : 0.f;
    }
}

// ================= fp32 SGEMM (double-buffered; store or atomic epilogue) ==
// C[m*ldc+n] (+)= sum_k A[m*lda+k] * B[n*ldb+k]
// store==1: C = acc + b1[n] (+b2[n]); store==0: atomicAdd into pre-init C.
#define BM 128
#define BN 128
#define BK 8

__global__ void __launch_bounds__(256, 2) sgemm(
    const float* __restrict__ A, long long lda,
    const float* __restrict__ B, long long ldb,
    const float* __restrict__ b1, const float* __restrict__ b2,
    float* __restrict__ C, long long ldc,
    int M, int N, int K, int kChunk, int store)
{
    __shared__ float As[2][BK][BM];
    __shared__ float Ws[2][BK][BN];
    int tid = threadIdx.x;
    int m0 = blockIdx.y * BM, n0 = blockIdx.x * BN;
    int kBeg = blockIdx.z * kChunk;
    int kEnd = min(K, kBeg + kChunk);
    if (kBeg >= kEnd) return;

    int ldRow = tid >> 1;
    int ldK   = (tid & 1) * 4;
    long long aRow = m0 + ldRow;
    long long bRow = n0 + ldRow;
    const float* Ap = A + aRow * lda;
    const float* Bp = B + bRow * ldb;
    bool aOk = aRow < M;
    bool bOk = bRow < N;

    int tr = tid >> 4, tc = tid & 15;
    float acc[8][8];
#pragma unroll
    for (int i = 0; i < 8; i++)
#pragma unroll
        for (int j = 0; j < 8; j++) acc[i][j] = 0.f;

    float pa[4], pb[4];
    ld4(Ap, kBeg + ldK, kEnd, aOk, pa);
    ld4(Bp, kBeg + ldK, kEnd, bOk, pb);
#pragma unroll
    for (int i = 0; i < 4; i++) {
        As[0][ldK + i][ldRow] = pa[i];
        Ws[0][ldK + i][ldRow] = pb[i];
    }
    __syncthreads();

    int cur = 0;
    for (int k0 = kBeg; k0 < kEnd; k0 += BK) {
        bool hasNext = (k0 + BK) < kEnd;
        if (hasNext) {
            ld4(Ap, k0 + BK + ldK, kEnd, aOk, pa);
            ld4(Bp, k0 + BK + ldK, kEnd, bOk, pb);
        }
#pragma unroll
        for (int kk = 0; kk < BK; kk++) {
            float4 x0 = *(const float4*)&As[cur][kk][tr * 4];
            float4 x1 = *(const float4*)&As[cur][kk][64 + tr * 4];
            float4 y0 = *(const float4*)&Ws[cur][kk][tc * 4];
            float4 y1 = *(const float4*)&Ws[cur][kk][64 + tc * 4];
            float aF[8] = {x0.x,x0.y,x0.z,x0.w,x1.x,x1.y,x1.z,x1.w};
            float wF[8] = {y0.x,y0.y,y0.z,y0.w,y1.x,y1.y,y1.z,y1.w};
#pragma unroll
            for (int i = 0; i < 8; i++)
#pragma unroll
                for (int j = 0; j < 8; j++)
                    acc[i][j] += aF[i] * wF[j];
        }
        if (hasNext) {
            int nxt = cur ^ 1;
#pragma unroll
            for (int i = 0; i < 4; i++) {
                As[nxt][ldK + i][ldRow] = pa[i];
                Ws[nxt][ldK + i][ldRow] = pb[i];
            }
        }
        __syncthreads();
        cur ^= 1;
    }

    if (store) {
        float bj[8];
#pragma unroll
        for (int j = 0; j < 8; j++) {
            int n = n0 + ((j < 4) ? (tc * 4 + j) : (64 + tc * 4 + j - 4));
            float v = 0.f;
            if (n < N) { v = b1[n]; if (b2) v += b2[n]; }
            bj[j] = v;
        }
        bool fullN = (n0 + BN) <= N;
#pragma unroll
        for (int i = 0; i < 8; i++) {
            int mloc = (i < 4) ? (tr * 4 + i) : (64 + tr * 4 + i - 4);
            long long m = m0 + mloc;
            if (m >= M) continue;
            float* cr = C + m * ldc;
            if (fullN) {
                float2 v;
                v.x = acc[i][0] + bj[0]; v.y = acc[i][1] + bj[1];
                *(float2*)&cr[n0 + tc * 4] = v;
                v.x = acc[i][2] + bj[2]; v.y = acc[i][3] + bj[3];
                *(float2*)&cr[n0 + tc * 4 + 2] = v;
                v.x = acc[i][4] + bj[4]; v.y = acc[i][5] + bj[5];
                *(float2*)&cr[n0 + 64 + tc * 4] = v;
                v.x = acc[i][6] + bj[6]; v.y = acc[i][7] + bj[7];
                *(float2*)&cr[n0 + 64 + tc * 4 + 2] = v;
            } else {
#pragma unroll
                for (int j = 0; j < 8; j++) {
                    int n = n0 + ((j < 4) ? (tc * 4 + j) : (64 + tc * 4 + j - 4));
                    if (n < N) cr[n] = acc[i][j] + bj[j];
                }
            }
        }
    } else {
#pragma unroll
        for (int i = 0; i < 8; i++) {
            int mloc = (i < 4) ? (tr * 4 + i) : (64 + tr * 4 + i - 4);
            long long m = m0 + mloc;
            if (m >= M) continue;
#pragma unroll
            for (int j = 0; j < 8; j++) {
                int n = n0 + ((j < 4) ? (tc * 4 + j) : (64 + tc * 4 + j - 4));
                if (n < N) atomicAdd(&C[m * ldc + n], acc[i][j]);
            }
        }
    }
}

// ---------------- skinny GEMM (M<=8), atomicAdd into C ----------------
#define SK_NT 32
#define SK_KC 1024
__global__ void __launch_bounds__(256) skinny_gemm_kernel(
    const float* __restrict__ A, long long sAm,
    const float* __restrict__ W, long long sWn,
    float* __restrict__ C, int M, int N, int K)
{
    __shared__ float As[8][SK_KC];
    int n0 = blockIdx.x * SK_NT;
    int k0 = blockIdx.y * SK_KC;
    int kLen = min(SK_KC, K - k0);
    int tid = threadIdx.x;
    for (int m = 0; m < M; m++)
        for (int k = tid; k < SK_KC; k += 256)
            As[m][k] = (k < kLen) ? A[(long long)m * sAm + k0 + k] : 0.f;
    __syncthreads();
    int warp = tid >> 5, lane = tid & 31;
    if (warp < M) {
        for (int nn = 0; nn < SK_NT; nn++) {
            int n = n0 + nn;
            if (n >= N) break;
            const float* wr = W + (long long)n * sWn + k0;
            float s = 0.f;
            for (int i = lane; i < kLen; i += 32) s += As[warp][i] * wr[i];
#pragma unroll
            for (int o = 16; o; o >>= 1) s += __shfl_xor_sync(0xffffffffu, s, o);
            if (lane == 0) atomicAdd(&C[warp * N + n], s);
        }
    }
}

// ---------------- transpose out_W [E,H] -> g_outWT [H,E] ----------------
__global__ void transpose_kernel(const float* __restrict__ src, float* __restrict__ dst)
{
    __shared__ float t[32][33];
    int r0 = blockIdx.y * 32, c0 = blockIdx.x * 32;
#pragma unroll
    for (int i = 0; i < 32; i += 8) {
        int r = r0 + threadIdx.y + i, c = c0 + threadIdx.x;
        if (r < EE && c < HH) t[threadIdx.y + i][threadIdx.x] = src[(long long)r * HH + c];
    }
    __syncthreads();
#pragma unroll
    for (int i = 0; i < 32; i += 8) {
        int rr = c0 + threadIdx.y + i, cc = r0 + threadIdx.x;
        if (rr < HH && cc < EE) dst[(long long)rr * EE + cc] = t[threadIdx.x][threadIdx.y + i];
    }
}

// ---------------- init / copy ----------------
__global__ void init_kernel(float* dst, const float* b1, int n, int period)
{
    int i = blockIdx.x * 256 + threadIdx.x;
    if (i < n) dst[i] = b1 ? b1[i % period] : 0.f;
}
__global__ void copy_hfinal_kernel()
{
    int i = blockIdx.x * 256 + threadIdx.x;
    if (i < BB * HH) {
        int b = i / HH, j = i % HH;
        g_hA[i] = g_enc[(b * TT + TT - 1) * HH + j];
    }
}
__global__ void copy_emb0_kernel()
{
    int i = blockIdx.x * 256 + threadIdx.x;
    if (i < BB * HH) g_emb[i] = g_nemb[i];
}

// ---------------- encoder recurrent step (float4 loads) ----------------
__global__ void __launch_bounds__(256) enc_step_kernel(const float* __restrict__ Whh, int t)
{
    const float* cIn  = (t & 1) ? g_cB : g_cA;
    float*       cOut = (t & 1) ? g_cA : g_cB;
    int warp = threadIdx.x >> 5, lane = threadIdx.x & 31;
    int j = blockIdx.x * 8 + warp;
    int gate = lane >> 3, b = lane & 7;
    float acc = 0.f;
    if (t > 0) {
        const float4* hr = (const float4*)(g_enc + (long long)(b * TT + t - 1) * HH);
        const float4* wr = (const float4*)(Whh + (long long)(gate * HH + j) * HH);
        float a0=0,a1=0,a2=0,a3=0;
#pragma unroll 2
        for (int k = 0; k < 250; k++) {
            float4 h = hr[k], w = wr[k];
            a0 += h.x*w.x; a1 += h.y*w.y; a2 += h.z*w.z; a3 += h.w*w.w;
        }
        acc = (a0+a1)+(a2+a3);
    }
    float gv = g_preg[(long long)(b * TT + t) * G4H + gate * HH + j] + acc;
    const unsigned F = 0xffffffffu;
    float gi = __shfl_sync(F, gv, b);
    float gf = __shfl_sync(F, gv, 8 + b);
    float gg = __shfl_sync(F, gv, 16 + b);
    float go = __shfl_sync(F, gv, 24 + b);
    if (gate == 0) {
        float c = sigmoidf_(gf) * cIn[b * HH + j] + sigmoidf_(gi) * tanhf(gg);
        cOut[b * HH + j] = c;
        g_enc[(long long)(b * TT + t) * HH + j] = sigmoidf_(go) * tanhf(c);
    }
}

// ---------------- decoder attention (block per b; float4 + coalesced) ------
__global__ void __launch_bounds__(256) dec_attn_kernel(const float* __restrict__ attnW, int s)
{
    const float* hIn = (s & 1) ? g_hB : g_hA;
    __shared__ __align__(16) float4 sx4[500];   // [emb(250) | h(250)]
    __shared__ float red[256];
    __shared__ float saw[TT];
    __shared__ float sval;
    int b = blockIdx.x, tid = threadIdx.x;
    if (tid < 250) {
        sx4[tid]       = ((const float4*)(g_emb + b * HH))[tid];
        sx4[250 + tid] = ((const float4*)(hIn + b * HH))[tid];
    }
    __syncthreads();
    int t = tid & 127, half = tid >> 7;
    {
        const float4* wr = (const float4*)(attnW + (long long)t * (3 * HH) + half * HH);
        const float4* xr = sx4 + half * 250;
        float a = 0.f;
#pragma unroll 2
        for (int k = 0; k < 250; k++) a += dot4_(xr[k], wr[k]);
        red[tid] = a;
    }
    __syncthreads();
    if (tid < 128) {
        float l = red[tid] + red[tid + 128] + g_n2l[(s * BB + b) * TT + tid];
        saw[tid] = l; red[tid] = l;
    }
    __syncthreads();
    for (int o = 64; o > 0; o >>= 1) {
        if (tid < o) red[tid] = fmaxf(red[tid], red[tid + o]);
        __syncthreads();
    }
    if (tid == 0) sval = red[0];
    __syncthreads();
    float mx = sval;
    if (tid < 128) { float e = expf(saw[tid] - mx); saw[tid] = e; red[tid] = e; }
    __syncthreads();
    for (int o = 64; o > 0; o >>= 1) {
        if (tid < o) red[tid] += red[tid + o];
        __syncthreads();
    }
    if (tid == 0) sval = red[0];
    __syncthreads();
    if (tid < 250) {
        float inv = 1.f / sval;
        const float* ep = g_enc + (long long)(b * TT) * HH + tid * 4;
        float4 a4 = make_float4(0.f, 0.f, 0.f, 0.f);
#pragma unroll 4
        for (int tt = 0; tt < TT; tt++) {
            float4 e = *(const float4*)(ep + (long long)tt * HH);
            float w = saw[tt];
            a4.x += w * e.x; a4.y += w * e.y; a4.z += w * e.z; a4.w += w * e.w;
        }
        a4.x *= inv; a4.y *= inv; a4.z *= inv; a4.w *= inv;
        ((float4*)(g_applied + b * HH))[tid] = a4;
    }
}

// ---------------- combine + relu (float4) ----------------
__global__ void __launch_bounds__(256) dec_comb_kernel(
    const float* __restrict__ combW, const float* __restrict__ combB)
{
    int warp = threadIdx.x >> 5, lane = threadIdx.x & 31;
    int j = blockIdx.x * 8 + warp;
    int b = lane & 7, ch = lane >> 3;
    const float4* wr = (const float4*)(combW + (long long)j * (2 * HH));
    const float4* xe = (const float4*)(g_emb + b * HH);
    const float4* xa = (const float4*)(g_applied + b * HH);
    float s = 0.f;
#pragma unroll 2
    for (int i = 0; i < 63; i++) {
        int k4 = ch + 4 * i;
        if (k4 < 250)
            s += dot4_(xe[k4], wr[k4]) + dot4_(xa[k4], wr[250 + k4]);
    }
    s += __shfl_xor_sync(0xffffffffu, s, 8);
    s += __shfl_xor_sync(0xffffffffu, s, 16);
    if (ch == 0) g_comb[b * HH + j] = fmaxf(s + combB[j], 0.f);
}

// ---------------- decoder LSTM step (float4) ----------------
__global__ void __launch_bounds__(256) dec_lstm_kernel(
    const float* __restrict__ Wih, const float* __restrict__ Whh,
    const float* __restrict__ bih, const float* __restrict__ bhh, int s)
{
    const float* hIn  = (s & 1) ? g_hB : g_hA;
    const float* cIn  = (s & 1) ? g_cB : g_cA;
    float*       hOut = (s & 1) ? g_hA : g_hB;
    float*       cOut = (s & 1) ? g_cA : g_cB;
    int warp = threadIdx.x >> 5, lane = threadIdx.x & 31;
    int j = blockIdx.x * 8 + warp;
    int gate = lane >> 3, b = lane & 7;
    int row = gate * HH + j;
    const float4* w1 = (const float4*)(Wih + (long long)row * HH);
    const float4* w2 = (const float4*)(Whh + (long long)row * HH);
    const float4* x1 = (const float4*)(g_comb + b * HH);
    const float4* x2 = (const float4*)(hIn + b * HH);
    float a0=0,a1=0,a2=0,a3=0;
#pragma unroll 2
    for (int k = 0; k < 250; k++) {
        float4 u1 = x1[k], v1 = w1[k], u2 = x2[k], v2 = w2[k];
        a0 += u1.x*v1.x + u2.x*v2.x;
        a1 += u1.y*v1.y + u2.y*v2.y;
        a2 += u1.z*v1.z + u2.z*v2.z;
        a3 += u1.w*v1.w + u2.w*v2.w;
    }
    float gv = (a0+a1)+(a2+a3) + bih[row] + bhh[row];
    const unsigned F = 0xffffffffu;
    float gi = __shfl_sync(F, gv, b);
    float gf = __shfl_sync(F, gv, 8 + b);
    float gg = __shfl_sync(F, gv, 16 + b);
    float go = __shfl_sync(F, gv, 24 + b);
    if (gate == 0) {
        float c = sigmoidf_(gf) * cIn[b * HH + j] + sigmoidf_(gi) * tanhf(gg);
        float h = sigmoidf_(go) * tanhf(c);
        cOut[b * HH + j] = c;
        hOut[b * HH + j] = h;
        g_Hs[(long long)(s * BB + b) * HH + j] = h;
    }
}

// ---------------- next-step emb via fused Mt (float4) ----------------
__global__ void __launch_bounds__(256) dec_embnext_kernel(int s, int snext)
{
    const float* hNew = (s & 1) ? g_hA : g_hB;
    int warp = threadIdx.x >> 5, lane = threadIdx.x & 31;
    int j = blockIdx.x * 8 + warp;
    int b = lane & 7, ch = lane >> 3;
    const float4* mr = (const float4*)(g_Mt + (long long)j * HH);
    const float4* hr = (const float4*)(hNew + b * HH);
    float s0 = 0.f;
#pragma unroll 2
    for (int i = 0; i < 63; i++) {
        int k4 = ch + 4 * i;
        if (k4 < 250) s0 += dot4_(hr[k4], mr[k4]);
    }
    s0 += __shfl_xor_sync(0xffffffffu, s0, 8);
    s0 += __shfl_xor_sync(0xffffffffu, s0, 16);
    if (ch == 0)
        g_emb[b * HH + j] = s0 + g_bias2[j] + g_nemb[(long long)(snext * BB + b) * HH + j];
}

// ---------------- launcher ----------------
extern "C" void kernel_launch(void* const* d_in, const int* in_sizes, int n_in,
                              void* d_out, int out_size)
{
    const float* input    = (const float*)d_in[0];
    const float* noise1   = (const float*)d_in[2];
    const float* noise2   = (const float*)d_in[3];
    const float* init_dec = (const float*)d_in[4];
    const float* eWih = (const float*)d_in[5];
    const float* eWhh = (const float*)d_in[6];
    const float* ebih = (const float*)d_in[7];
    const float* ebhh = (const float*)d_in[8];
    const float* dWih = (const float*)d_in[9];
    const float* dWhh = (const float*)d_in[10];
    const float* dbih = (const float*)d_in[11];
    const float* dbhh = (const float*)d_in[12];
    const float* embW = (const float*)d_in[13];
    const float* embb = (const float*)d_in[14];
    const float* attW = (const float*)d_in[15];
    const float* attb = (const float*)d_in[16];
    const float* combW = (const float*)d_in[17];
    const float* combb = (const float*)d_in[18];
    const float* outW = (const float*)d_in[19];
    const float* outb = (const float*)d_in[20];
    float* out = (float*)d_out;

    float *preg, *Mt, *nemb, *n2l, *bias2, *emb, *Hs, *cA, *outWT;
    cudaGetSymbolAddress((void**)&preg,   g_preg);
    cudaGetSymbolAddress((void**)&Mt,     g_Mt);
    cudaGetSymbolAddress((void**)&nemb,   g_nemb);
    cudaGetSymbolAddress((void**)&n2l,    g_n2l);
    cudaGetSymbolAddress((void**)&bias2,  g_bias2);
    cudaGetSymbolAddress((void**)&emb,    g_emb);
    cudaGetSymbolAddress((void**)&Hs,     g_Hs);
    cudaGetSymbolAddress((void**)&cA,     g_cA);
    cudaGetSymbolAddress((void**)&outWT,  g_outWT);

    // ncu capture: harness injects 2 launches; -s 5 lands on my launch #3.
    init_kernel<<<(BB*HH + 255) / 256, 256>>>(cA, nullptr, BB*HH, 1);            // #0
    init_kernel<<<(HH*HH + 255) / 256, 256>>>(Mt, nullptr, HH*HH, 1);            // #1
    transpose_kernel<<<dim3((HH + 31) / 32, (EE + 31) / 32), dim3(32, 8)>>>(outW, outWT); // #2
    // #3 (profiled): preg = input @ eWih^T + ebih + ebhh  (store mode)
    sgemm<<<dim3(32, 8, 1), 256>>>(input, EE, eWih, EE, ebih, ebhh,
                                   preg, G4H, BB*TT, G4H, EE, EE, 1);

    init_kernel<<<(SS*BB*HH + 255) / 256, 256>>>(nemb, embb, SS*BB*HH, HH);
    init_kernel<<<(SS*BB*TT + 255) / 256, 256>>>(n2l, attb, SS*BB*TT, TT);
    init_kernel<<<(HH + 255) / 256, 256>>>(bias2, nullptr, HH, 1);

    // Mt = embW_E @ outWT^T (atomic, k-split)
    sgemm<<<dim3(8, 8, 8), 256>>>(embW, EN, outWT, EE, nullptr, nullptr,
                                  Mt, HH, HH, HH, EE, 3816, 0);
    // nemb += noise1 @ embW_nz^T
    sgemm<<<dim3(8, 4, 8), 256>>>(noise1, NZ, embW + EE, EN, nullptr, nullptr,
                                  nemb, HH, SS*BB, HH, NZ, 1250, 0);
    // n2l += noise2 @ attW[:,2H:]^T
    sgemm<<<dim3(1, 4, 8), 256>>>(noise2, HH, attW + 2*HH, 3*HH, nullptr, nullptr,
                                  n2l, TT, SS*BB, TT, HH, 126, 0);

    // bias2 = emb_W_E @ out_b
    skinny_gemm_kernel<<<dim3(32, 30), 256>>>(outb, 0, embW, EN, bias2, 1, HH, EE);

    // encoder recurrence
    for (int t = 0; t < TT; t++)
        enc_step_kernel<<<125, 256>>>(eWhh, t);
    copy_hfinal_kernel<<<(BB*HH + 255) / 256, 256>>>();

    // decoder step-0 emb
    copy_emb0_kernel<<<(BB*HH + 255) / 256, 256>>>();
    skinny_gemm_kernel<<<dim3(32, 30), 256>>>(init_dec, EE, embW, EN, emb, BB, HH, EE);

    for (int s = 0; s < SS; s++) {
        dec_attn_kernel<<<BB, 256>>>(attW, s);
        dec_comb_kernel<<<125, 256>>>(combW, combb);
        dec_lstm_kernel<<<125, 256>>>(dWih, dWhh, dbih, dbhh, s);
        if (s + 1 < SS) dec_embnext_kernel<<<125, 256>>>(s, s + 1);
    }

    // out = Hs @ out_W^T + out_b (store mode)
    sgemm<<<dim3(239, 4, 1), 256>>>(Hs, HH, outW, HH, outb, nullptr,
                                    out, EE, SS*BB, EE, HH, HH, 1);
}